// round 1
// baseline (speedup 1.0000x reference)
#include <cuda_runtime.h>
#include <stdint.h>

// Problem constants
#define B_ 8
#define N_ 512
#define D_ 768
#define A_ 12
#define E_ 64
#define M_ (B_ * N_)   // 4096

// Scratch (device globals: allocation-free)
__device__ float g_h[B_ * A_ * N_ * E_];     // [b][a][i][e]  12.6 MB
__device__ float g_src[B_ * A_ * N_];
__device__ float g_dst[B_ * A_ * N_];
__device__ float g_att[B_ * N_ * D_];        // [b][i][a*64+e] (attn@h + bias b)
__device__ int   g_adj_int;

// ---------------------------------------------------------------------------
// adj dtype detection: int32 0/1 words => int layout; packed bool bytes give
// words like 0x00010001 which are neither 0 nor 1.
// ---------------------------------------------------------------------------
__global__ void detect_adj_kernel(const int* __restrict__ adj) {
    int ok = 1;
    for (int v = threadIdx.x; v < 1024; v += 32) {
        int w = adj[v];
        if (w != 0 && w != 1) ok = 0;
    }
#pragma unroll
    for (int o = 16; o; o >>= 1) ok &= __shfl_xor_sync(0xffffffffu, ok, o);
    if (threadIdx.x == 0) g_adj_int = ok;
}

// ---------------------------------------------------------------------------
// GEMM-1: h[b,i,a,e] = sum_d feat[b,i,d] * W[a,d,e]
// 4096x768 x 768x768 ; B matrix addressed as W[(n>>6)*768*64 + k*64 + (n&63)]
// 128x128x16 tiles, 256 threads, 8x8 per thread, double-buffered smem.
// ---------------------------------------------------------------------------
__global__ __launch_bounds__(256, 2) void gemm_h_kernel(const float* __restrict__ Af,
                                                        const float* __restrict__ W) {
    __shared__ float As[2][16][128];
    __shared__ float Bs[2][16][128];
    const int tid = threadIdx.x;
    const int m0 = blockIdx.y << 7;
    const int n0 = blockIdx.x << 7;

    const int arow = tid >> 2;
    const int acol = (tid & 3) << 2;
    const float* Ap0 = Af + (m0 + arow) * D_ + acol;
    const float* Ap1 = Ap0 + 64 * D_;

    const int bk = tid >> 5;                 // 0..7
    const int bn = (tid & 31) << 2;          // 0..124
    const int head = (n0 + bn) >> 6;
    const int be = (n0 + bn) & 63;
    const float* Wp0 = W + (head * D_ + bk) * E_ + be;
    const float* Wp1 = Wp0 + 8 * E_;

    float4 pa0 = *(const float4*)Ap0;
    float4 pa1 = *(const float4*)Ap1;
    float4 pb0 = *(const float4*)Wp0;
    float4 pb1 = *(const float4*)Wp1;

    const int txb = (tid & 15) << 3;
    const int tyb = (tid >> 4) << 3;

    float acc[8][8];
#pragma unroll
    for (int i = 0; i < 8; ++i)
#pragma unroll
        for (int j = 0; j < 8; ++j) acc[i][j] = 0.f;

#define STORE_AB1(s) do {                                                     \
    As[s][acol+0][arow] = pa0.x; As[s][acol+1][arow] = pa0.y;                 \
    As[s][acol+2][arow] = pa0.z; As[s][acol+3][arow] = pa0.w;                 \
    As[s][acol+0][arow+64] = pa1.x; As[s][acol+1][arow+64] = pa1.y;           \
    As[s][acol+2][arow+64] = pa1.z; As[s][acol+3][arow+64] = pa1.w;           \
    *(float4*)&Bs[s][bk][bn] = pb0;                                           \
    *(float4*)&Bs[s][bk+8][bn] = pb1; } while (0)

    STORE_AB1(0);
    __syncthreads();

    const int KT = D_ / 16;  // 48
    for (int kt = 0; kt < KT; ++kt) {
        const int s = kt & 1;
        if (kt + 1 < KT) {
            Ap0 += 16; Ap1 += 16;
            Wp0 += 16 * E_; Wp1 += 16 * E_;
            pa0 = *(const float4*)Ap0;
            pa1 = *(const float4*)Ap1;
            pb0 = *(const float4*)Wp0;
            pb1 = *(const float4*)Wp1;
        }
#pragma unroll
        for (int k = 0; k < 16; ++k) {
            alignas(16) float ra[8], rb[8];
            *(float4*)&ra[0] = *(const float4*)&As[s][k][tyb];
            *(float4*)&ra[4] = *(const float4*)&As[s][k][tyb + 4];
            *(float4*)&rb[0] = *(const float4*)&Bs[s][k][txb];
            *(float4*)&rb[4] = *(const float4*)&Bs[s][k][txb + 4];
#pragma unroll
            for (int i = 0; i < 8; ++i)
#pragma unroll
                for (int j = 0; j < 8; ++j)
                    acc[i][j] = fmaf(ra[i], rb[j], acc[i][j]);
        }
        if (kt + 1 < KT) STORE_AB1(s ^ 1);
        __syncthreads();
    }
#undef STORE_AB1

    // epilogue: scatter to g_h[b][a][i][e]
    const int bidx = m0 >> 9;  // block fits in one b (128 < 512)
#pragma unroll
    for (int i = 0; i < 8; ++i) {
        const int m = m0 + tyb + i;
        const int irow = m & (N_ - 1);
#pragma unroll
        for (int jv = 0; jv < 8; jv += 4) {
            const int n = n0 + txb + jv;
            float4 v = make_float4(acc[i][jv], acc[i][jv + 1], acc[i][jv + 2], acc[i][jv + 3]);
            *(float4*)&g_h[(((bidx * A_) + (n >> 6)) * N_ + irow) * E_ + (n & 63)] = v;
        }
    }
}

// ---------------------------------------------------------------------------
// src/dst: warp per (b,a,i) row: tanh(h) . w_src / w_dst
// ---------------------------------------------------------------------------
__global__ void srcdst_kernel(const float* __restrict__ wsrc, const float* __restrict__ wdst) {
    const int warp = (blockIdx.x * blockDim.x + threadIdx.x) >> 5;
    const int lane = threadIdx.x & 31;
    const int a = (warp >> 9) % A_;
    const float* hr = g_h + (size_t)warp * E_;
    float t0 = tanhf(hr[lane]);
    float t1 = tanhf(hr[lane + 32]);
    float s = t0 * __ldg(wsrc + a * E_ + lane) + t1 * __ldg(wsrc + a * E_ + lane + 32);
    float d = t0 * __ldg(wdst + a * E_ + lane) + t1 * __ldg(wdst + a * E_ + lane + 32);
#pragma unroll
    for (int o = 16; o; o >>= 1) {
        s += __shfl_xor_sync(0xffffffffu, s, o);
        d += __shfl_xor_sync(0xffffffffu, d, o);
    }
    if (lane == 0) { g_src[warp] = s; g_dst[warp] = d; }
}

// ---------------------------------------------------------------------------
// Attention: block = (isplit, a, b). h[b,a] tile (128KB) in smem.
// Per row i: logits, masked leaky-relu, softmax, attn @ h -> g_att.
// ---------------------------------------------------------------------------
#define ISPLIT 4
#define ATT_SMEM_FLOATS (N_ * E_ + N_ + N_ + 256 + 16)

__global__ __launch_bounds__(256) void attn_kernel(const void* __restrict__ adjv,
                                                   const float* __restrict__ bbias) {
    extern __shared__ float sm[];
    float* sh_h = sm;                    // 32768
    float* sh_dst = sm + N_ * E_;        // 512
    float* sh_p = sh_dst + N_;           // 512
    float* sh_red = sh_p + N_;           // 256
    float* sh_w = sh_red + 256;          // 16

    const int tid = threadIdx.x;
    const int b = blockIdx.z, a = blockIdx.y;
    const int ba = b * A_ + a;

    const float4* hsrc = (const float4*)(g_h + (size_t)ba * N_ * E_);
    for (int v = tid; v < N_ * E_ / 4; v += 256) ((float4*)sh_h)[v] = hsrc[v];
    sh_dst[tid] = g_dst[ba * N_ + tid];
    sh_dst[tid + 256] = g_dst[ba * N_ + tid + 256];
    __syncthreads();

    const int lane = tid & 31, wid = tid >> 5;
    const int e = tid & 63, jg = tid >> 6;
    const int adj_int = g_adj_int;
    const uint8_t* adj8 = (const uint8_t*)adjv;
    const int* adj32 = (const int*)adjv;

    const int i0 = blockIdx.x * (N_ / ISPLIT);
    for (int i = i0; i < i0 + N_ / ISPLIT; ++i) {
        const float si = __ldg(&g_src[ba * N_ + i]);
        const int rowoff = (b * N_ + i) * N_;
        bool c0, c1;
        if (adj_int) { c0 = adj32[rowoff + tid] != 0; c1 = adj32[rowoff + tid + 256] != 0; }
        else         { c0 = adj8[rowoff + tid] != 0;  c1 = adj8[rowoff + tid + 256] != 0; }
        float l0 = si + sh_dst[tid];
        float l1 = si + sh_dst[tid + 256];
        l0 = l0 >= 0.f ? l0 : 0.2f * l0;
        l1 = l1 >= 0.f ? l1 : 0.2f * l1;
        if (!c0) l0 = -999.f;
        if (!c1) l1 = -999.f;

        float mx = fmaxf(l0, l1);
#pragma unroll
        for (int o = 16; o; o >>= 1) mx = fmaxf(mx, __shfl_xor_sync(0xffffffffu, mx, o));
        if (lane == 0) sh_w[wid] = mx;
        __syncthreads();
        float rmax = sh_w[0];
#pragma unroll
        for (int w = 1; w < 8; ++w) rmax = fmaxf(rmax, sh_w[w]);

        float p0 = __expf(l0 - rmax);
        float p1 = __expf(l1 - rmax);
        sh_p[tid] = p0;
        sh_p[tid + 256] = p1;
        float ssum = p0 + p1;
#pragma unroll
        for (int o = 16; o; o >>= 1) ssum += __shfl_xor_sync(0xffffffffu, ssum, o);
        if (lane == 0) sh_w[8 + wid] = ssum;
        __syncthreads();
        float denom = sh_w[8];
#pragma unroll
        for (int w = 1; w < 8; ++w) denom += sh_w[8 + w];
        const float inv = __fdividef(1.f, denom);

        const float* hp = sh_h + (jg << 7) * E_ + e;
        const float* pp = sh_p + (jg << 7);
        float acc = 0.f;
#pragma unroll 8
        for (int jj = 0; jj < 128; ++jj) acc = fmaf(pp[jj], hp[jj * E_], acc);
        sh_red[tid] = acc;
        __syncthreads();
        if (jg == 0) {
            float tot = (sh_red[e] + sh_red[64 + e]) + (sh_red[128 + e] + sh_red[192 + e]);
            g_att[(size_t)(b * N_ + i) * D_ + a * E_ + e] = fmaf(tot, inv, __ldg(bbias + e));
        }
        __syncthreads();
    }
}

// ---------------------------------------------------------------------------
// GEMM-2 + fused epilogue: gate = sigmoid(feat @ H_w^T + H_b);
// out = gate * elu(g_att) + (1-gate) * feat
// ---------------------------------------------------------------------------
__device__ __forceinline__ float blend_one(float accv, float hb, float att, float f) {
    float g = 1.f / (1.f + __expf(-(accv + hb)));
    float fo = att > 0.f ? att : (__expf(att) - 1.f);
    return g * fo + (1.f - g) * f;
}

__global__ __launch_bounds__(256, 2) void gemm_gate_kernel(const float* __restrict__ Af,
                                                           const float* __restrict__ Hw,
                                                           const float* __restrict__ Hb,
                                                           float* __restrict__ out) {
    __shared__ float As[2][16][128];
    __shared__ float Bs[2][16][128];
    const int tid = threadIdx.x;
    const int m0 = blockIdx.y << 7;
    const int n0 = blockIdx.x << 7;

    const int arow = tid >> 2;
    const int acol = (tid & 3) << 2;
    const float* Ap0 = Af + (m0 + arow) * D_ + acol;
    const float* Ap1 = Ap0 + 64 * D_;

    const int hn = tid >> 1;             // 0..127
    const int hkv = (tid & 1) << 3;      // 0 or 8
    const float* Hp = Hw + (n0 + hn) * D_ + hkv;

    float4 pa0 = *(const float4*)Ap0;
    float4 pa1 = *(const float4*)Ap1;
    float4 pb0 = *(const float4*)Hp;
    float4 pb1 = *(const float4*)(Hp + 4);

    const int txb = (tid & 15) << 3;
    const int tyb = (tid >> 4) << 3;

    float acc[8][8];
#pragma unroll
    for (int i = 0; i < 8; ++i)
#pragma unroll
        for (int j = 0; j < 8; ++j) acc[i][j] = 0.f;

#define STORE_AB2(s) do {                                                     \
    As[s][acol+0][arow] = pa0.x; As[s][acol+1][arow] = pa0.y;                 \
    As[s][acol+2][arow] = pa0.z; As[s][acol+3][arow] = pa0.w;                 \
    As[s][acol+0][arow+64] = pa1.x; As[s][acol+1][arow+64] = pa1.y;           \
    As[s][acol+2][arow+64] = pa1.z; As[s][acol+3][arow+64] = pa1.w;           \
    Bs[s][hkv+0][hn] = pb0.x; Bs[s][hkv+1][hn] = pb0.y;                       \
    Bs[s][hkv+2][hn] = pb0.z; Bs[s][hkv+3][hn] = pb0.w;                       \
    Bs[s][hkv+4][hn] = pb1.x; Bs[s][hkv+5][hn] = pb1.y;                       \
    Bs[s][hkv+6][hn] = pb1.z; Bs[s][hkv+7][hn] = pb1.w; } while (0)

    STORE_AB2(0);
    __syncthreads();

    const int KT = D_ / 16;  // 48
    for (int kt = 0; kt < KT; ++kt) {
        const int s = kt & 1;
        if (kt + 1 < KT) {
            Ap0 += 16; Ap1 += 16; Hp += 16;
            pa0 = *(const float4*)Ap0;
            pa1 = *(const float4*)Ap1;
            pb0 = *(const float4*)Hp;
            pb1 = *(const float4*)(Hp + 4);
        }
#pragma unroll
        for (int k = 0; k < 16; ++k) {
            alignas(16) float ra[8], rb[8];
            *(float4*)&ra[0] = *(const float4*)&As[s][k][tyb];
            *(float4*)&ra[4] = *(const float4*)&As[s][k][tyb + 4];
            *(float4*)&rb[0] = *(const float4*)&Bs[s][k][txb];
            *(float4*)&rb[4] = *(const float4*)&Bs[s][k][txb + 4];
#pragma unroll
            for (int i = 0; i < 8; ++i)
#pragma unroll
                for (int j = 0; j < 8; ++j)
                    acc[i][j] = fmaf(ra[i], rb[j], acc[i][j]);
        }
        if (kt + 1 < KT) STORE_AB2(s ^ 1);
        __syncthreads();
    }
#undef STORE_AB2

#pragma unroll
    for (int i = 0; i < 8; ++i) {
        const int m = m0 + tyb + i;
        const float* attp = g_att + (size_t)m * D_ + n0 + txb;
        const float* fp = Af + (size_t)m * D_ + n0 + txb;
        float* op = out + (size_t)m * D_ + n0 + txb;
#pragma unroll
        for (int jv = 0; jv < 8; jv += 4) {
            float4 av = *(const float4*)(attp + jv);
            float4 fv = *(const float4*)(fp + jv);
            float4 hb = *(const float4*)(Hb + n0 + txb + jv);
            float4 ov;
            ov.x = blend_one(acc[i][jv + 0], hb.x, av.x, fv.x);
            ov.y = blend_one(acc[i][jv + 1], hb.y, av.y, fv.y);
            ov.z = blend_one(acc[i][jv + 2], hb.z, av.z, fv.z);
            ov.w = blend_one(acc[i][jv + 3], hb.w, av.w, fv.w);
            *(float4*)(op + jv) = ov;
        }
    }
}

// ---------------------------------------------------------------------------
extern "C" void kernel_launch(void* const* d_in, const int* in_sizes, int n_in,
                              void* d_out, int out_size) {
    const float* feat = (const float*)d_in[0];
    const void* adj = d_in[1];
    const float* W = (const float*)d_in[2];
    const float* bbias = (const float*)d_in[3];
    const float* wsrc = (const float*)d_in[4];
    const float* wdst = (const float*)d_in[5];
    const float* Hw = (const float*)d_in[6];
    const float* Hb = (const float*)d_in[7];
    float* out = (float*)d_out;

    detect_adj_kernel<<<1, 32>>>((const int*)adj);
    gemm_h_kernel<<<dim3(D_ / 128, M_ / 128), 256>>>(feat, W);
    srcdst_kernel<<<(B_ * A_ * N_) / 8, 256>>>(wsrc, wdst);

    const size_t att_smem = (size_t)ATT_SMEM_FLOATS * sizeof(float);
    cudaFuncSetAttribute(attn_kernel, cudaFuncAttributeMaxDynamicSharedMemorySize, (int)att_smem);
    attn_kernel<<<dim3(ISPLIT, A_, B_), 256, att_smem>>>(adj, bbias);

    gemm_gate_kernel<<<dim3(D_ / 128, M_ / 128), 256>>>(feat, Hw, Hb, out);
}